// round 12
// baseline (speedup 1.0000x reference)
#include <cuda_runtime.h>
#include <cuda_fp16.h>
#include <cuda_bf16.h>

#define N_NODES 50000
#define DIM     128
#define N_EDGES 800000
#define TILE    512
#define TILES_PER_G 98          // ceil(50000/512)
#define N_TILES (2 * TILES_PER_G)
#define GM      128             // GEMM block M
#define NBLK    ((N_NODES + GM - 1) / GM)   // 391

// ---------------------------------------------------------------------------
// Scratch (device globals — no allocation allowed in kernel_launch)
// ---------------------------------------------------------------------------
__device__ int    g_cnt [2 * N_NODES];
__device__ int    g_offs[2 * (N_NODES + 1)];
__device__ int    g_cur [2 * N_NODES];
__device__ int    g_csr [2 * N_EDGES];
__device__ float  g_dinv[2 * N_NODES];
__device__ __half g_hsA [N_NODES * DIM];     // (x @ W) * dinv[row]  (fp16), graph 1
__device__ __half g_hsB [N_NODES * DIM];     // graph 2
__device__ float  g_h1  [N_NODES * DIM];     // hidden activations graph 1
__device__ float  g_h2  [N_NODES * DIM];     // graph 2
__device__ int    g_tilesum [N_TILES];
__device__ int    g_tilebase[N_TILES];
// B fragments, nb-paired: [layer][kc(4)][ks(4)][wnh(2)][nbp(4)][g(8)][l4(4)]
//   uint4 = {b0(nb), b1(nb), b0(nb+1), b1(nb+1)}, n = wnh*64 + nb*8 + g
__device__ uint4  g_Bq[2 * 4096];

// ---------------------------------------------------------------------------
// tf32 helpers
// ---------------------------------------------------------------------------
__device__ __forceinline__ unsigned f2tf(float f) {
    unsigned r;
    asm("cvt.rna.tf32.f32 %0, %1;" : "=r"(r) : "f"(f));
    return r;
}

__device__ __forceinline__ void mma8(float c[4], const unsigned a[4],
                                     unsigned b0, unsigned b1) {
    asm volatile(
        "mma.sync.aligned.m16n8k8.row.col.f32.tf32.tf32.f32 "
        "{%0,%1,%2,%3}, {%4,%5,%6,%7}, {%8,%9}, {%0,%1,%2,%3};"
        : "+f"(c[0]), "+f"(c[1]), "+f"(c[2]), "+f"(c[3])
        : "r"(a[0]), "r"(a[1]), "r"(a[2]), "r"(a[3]), "r"(b0), "r"(b1));
}

// ---------------------------------------------------------------------------
// W pre-pack (tf32-rounded, nb-paired fragments)
// ---------------------------------------------------------------------------
__global__ void k_splitw(const float* __restrict__ W0, const float* __restrict__ W1) {
    int i = blockIdx.x * blockDim.x + threadIdx.x;
    if (i >= 8192) return;
    const float* W = (i < 4096) ? W0 : W1;
    int j   = i & 4095;
    int l4  = j & 3;
    int g   = (j >> 2) & 7;
    int nbp = (j >> 5) & 3;
    int wnh = (j >> 7) & 1;
    int ks  = (j >> 8) & 3;
    int kc  = j >> 10;
    int k0  = kc * 32 + ks * 8;
    int n0  = wnh * 64 + (2 * nbp) * 8 + g;
    int n1  = n0 + 8;
    uint4 v;
    v.x = f2tf(W[(k0 + l4)     * 128 + n0]);
    v.y = f2tf(W[(k0 + l4 + 4) * 128 + n0]);
    v.z = f2tf(W[(k0 + l4)     * 128 + n1]);
    v.w = f2tf(W[(k0 + l4 + 4) * 128 + n1]);
    g_Bq[i] = v;
}

// ---------------------------------------------------------------------------
// CSR build
// ---------------------------------------------------------------------------
__global__ void k_zero_cnt() {
    int i = blockIdx.x * blockDim.x + threadIdx.x;
    if (i < 2 * N_NODES) g_cnt[i] = 0;
}

__global__ void k_count2(const int* __restrict__ dst1, const int* __restrict__ dst2) {
    int i = blockIdx.x * blockDim.x + threadIdx.x;
    int stride = gridDim.x * blockDim.x;
    for (; i < 2 * N_EDGES; i += stride) {
        if (i < N_EDGES) atomicAdd(&g_cnt[__ldg(dst1 + i)], 1);
        else             atomicAdd(&g_cnt[N_NODES + __ldg(dst2 + i - N_EDGES)], 1);
    }
}

__global__ __launch_bounds__(TILE)
void k_blocksum() {
    int g  = blockIdx.x / TILES_PER_G;
    int lt = blockIdx.x % TILES_PER_G;
    int li = lt * TILE + threadIdx.x;
    int c = (li < N_NODES) ? g_cnt[g * N_NODES + li] : 0;

    int lane = threadIdx.x & 31, w = threadIdx.x >> 5;
    for (int o = 16; o > 0; o >>= 1) c += __shfl_down_sync(~0u, c, o);
    __shared__ int ws[TILE / 32];
    if (lane == 0) ws[w] = c;
    __syncthreads();
    if (threadIdx.x == 0) {
        int s = 0;
#pragma unroll
        for (int i = 0; i < TILE / 32; i++) s += ws[i];
        g_tilesum[blockIdx.x] = s;
    }
}

__global__ __launch_bounds__(256)
void k_scanbase() {
    __shared__ int s[N_TILES];
    if (threadIdx.x < N_TILES) s[threadIdx.x] = g_tilesum[threadIdx.x];
    __syncthreads();
    if (threadIdx.x < 2) {
        int g = threadIdx.x;
        int run = 0;
        for (int t = 0; t < TILES_PER_G; t++) {
            g_tilebase[g * TILES_PER_G + t] = run;
            run += s[g * TILES_PER_G + t];
        }
        g_offs[g * (N_NODES + 1) + N_NODES] = run;
    }
}

__global__ __launch_bounds__(TILE)
void k_offsets() {
    int g  = blockIdx.x / TILES_PER_G;
    int lt = blockIdx.x % TILES_PER_G;
    int li = lt * TILE + threadIdx.x;
    int c = (li < N_NODES) ? g_cnt[g * N_NODES + li] : 0;

    int lane = threadIdx.x & 31, w = threadIdx.x >> 5;
    int v = c;
#pragma unroll
    for (int o = 1; o < 32; o <<= 1) {
        int t = __shfl_up_sync(~0u, v, o);
        if (lane >= o) v += t;
    }
    __shared__ int ws[TILE / 32];
    if (lane == 31) ws[w] = v;
    __syncthreads();
    if (w == 0 && lane < TILE / 32) {
        int s = ws[lane];
#pragma unroll
        for (int o = 1; o < TILE / 32; o <<= 1) {
            int t = __shfl_up_sync(0xffff, s, o);
            if (lane >= o) s += t;
        }
        ws[lane] = s;
    }
    __syncthreads();
    int excl = v - c + (w > 0 ? ws[w - 1] : 0);

    if (li < N_NODES) {
        int off = g_tilebase[blockIdx.x] + excl;
        g_offs[g * (N_NODES + 1) + li] = off;
        g_cur [g * N_NODES + li] = off;
        g_dinv[g * N_NODES + li] = rsqrtf(1.0f + (float)c);
    }
}

__global__ void k_fill2(const int* __restrict__ src1, const int* __restrict__ dst1,
                        const int* __restrict__ src2, const int* __restrict__ dst2) {
    int i = blockIdx.x * blockDim.x + threadIdx.x;
    int stride = gridDim.x * blockDim.x;
    for (; i < 2 * N_EDGES; i += stride) {
        if (i < N_EDGES) {
            int d = __ldg(dst1 + i);
            int p = atomicAdd(&g_cur[d], 1);
            g_csr[p] = __ldg(src1 + i);
        } else {
            int e = i - N_EDGES;
            int d = __ldg(dst2 + e);
            int p = atomicAdd(&g_cur[N_NODES + d], 1);
            g_csr[N_EDGES + p] = __ldg(src2 + e);
        }
    }
}

// ---------------------------------------------------------------------------
// GEMM (single-pass TF32, fragment-native A, nb-paired B -> LDS.128 only).
// hs[m][:] = (x[m][:] @ W) * dinv[m], dinv computed on the fly from g_cnt
// (rsqrtf(1+cnt)) so the GEMM needs only counts, not the CSR. fp16 output.
// smem: A 16KB + B 16KB = 32KB.
// ---------------------------------------------------------------------------
__global__ __launch_bounds__(256, 2)
void k_gemm_tf32(const float* __restrict__ xA, const float* __restrict__ xB,
                 const uint4* __restrict__ Bq, const int* __restrict__ cntAB,
                 __half* __restrict__ hsA, __half* __restrict__ hsB) {
    __shared__ uint4 xs[8 * 4 * 32];   // [(mb*4+ks)*32 + lane_rot] = {a0,a1,a2,a3}
    __shared__ uint4 Bs[1024];         // [ks][wnh][nbp][g][l4] nb-paired fragments

    const int tid  = threadIdx.x;
    const int lane = tid & 31;
    const int wid  = tid >> 5;
    const int g    = lane >> 2;
    const int l4   = lane & 3;
    const int wm   = (wid & 3) * 32;
    const int wnh  = wid >> 2;
    const int wn   = wnh * 64;

    const int gph  = (blockIdx.x >= NBLK) ? 1 : 0;
    const int m0   = (blockIdx.x - gph * NBLK) * GM;
    const float* x = gph ? xB : xA;
    __half* hs     = gph ? hsB : hsA;
    const int* cnt = cntAB + gph * N_NODES;

    float c[2][8][4];
#pragma unroll
    for (int mf = 0; mf < 2; mf++)
#pragma unroll
        for (int nb = 0; nb < 8; nb++)
#pragma unroll
            for (int q = 0; q < 4; q++) c[mf][nb][q] = 0.0f;

    for (int kc = 0; kc < 4; kc++) {
#pragma unroll
        for (int j = 0; j < 4; j++)
            Bs[tid + j * 256] = __ldg(Bq + kc * 1024 + tid + j * 256);

        // Fill A in fragment-native layout (tf32-convert once, at fill time)
        unsigned* xsu = (unsigned*)xs;
#pragma unroll
        for (int i = 0; i < 4; i++) {
            int f  = i * 256 + tid;
            int r  = f >> 3;           // row in tile (0..127)
            int cc = f & 7;            // float4 column (k = cc*4 + j)
            int R  = m0 + r;
            float4 v = make_float4(0.f, 0.f, 0.f, 0.f);
            if (R < N_NODES)
                v = __ldg((const float4*)x + (size_t)R * 32 + kc * 8 + cc);
            int rr   = r & 15;
            int mb   = r >> 4;                    // 16-row block (0..7)
            int g2   = rr & 7;
            int slot = (rr >> 3) + (cc & 1) * 2;  // a0/a1/a2/a3
            int ks   = cc >> 1;
            int base = (mb * 4 + ks) * 32;
            unsigned t0 = f2tf(v.x), t1 = f2tf(v.y), t2 = f2tf(v.z), t3 = f2tf(v.w);
            xsu[((base + ((g2 * 4 + 0 + ks * 2) & 31)) << 2) + slot] = t0;
            xsu[((base + ((g2 * 4 + 1 + ks * 2) & 31)) << 2) + slot] = t1;
            xsu[((base + ((g2 * 4 + 2 + ks * 2) & 31)) << 2) + slot] = t2;
            xsu[((base + ((g2 * 4 + 3 + ks * 2) & 31)) << 2) + slot] = t3;
        }
        __syncthreads();

#pragma unroll
        for (int ks = 0; ks < 4; ks++) {
            unsigned afrag[2][4];
#pragma unroll
            for (int mf = 0; mf < 2; mf++) {
                int mb = (wid & 3) * 2 + mf;
                uint4 a = xs[(mb * 4 + ks) * 32 + ((lane + ks * 2) & 31)];
                afrag[mf][0] = a.x; afrag[mf][1] = a.y;
                afrag[mf][2] = a.z; afrag[mf][3] = a.w;
            }
#pragma unroll
            for (int nbp = 0; nbp < 4; nbp++) {
                uint4 bb = Bs[((ks * 2 + wnh) * 4 + nbp) * 32 + g * 4 + l4];
#pragma unroll
                for (int mf = 0; mf < 2; mf++) {
                    mma8(c[mf][2 * nbp],     afrag[mf], bb.x, bb.y);
                    mma8(c[mf][2 * nbp + 1], afrag[mf], bb.z, bb.w);
                }
            }
        }
        __syncthreads();
    }

    // Epilogue: scale by dinv[row] = rsqrt(1+cnt[row]), store fp16
#pragma unroll
    for (int mf = 0; mf < 2; mf++) {
        int R0 = m0 + wm + mf * 16 + g;
        int R1 = R0 + 8;
        float d0 = (R0 < N_NODES) ? rsqrtf(1.0f + (float)__ldg(cnt + R0)) : 0.f;
        float d1 = (R1 < N_NODES) ? rsqrtf(1.0f + (float)__ldg(cnt + R1)) : 0.f;
#pragma unroll
        for (int nb = 0; nb < 8; nb++) {
            int col = wn + nb * 8 + 2 * l4;
            if (R0 < N_NODES) {
                __half2 o = __floats2half2_rn(c[mf][nb][0] * d0, c[mf][nb][1] * d0);
                *(__half2*)(hs + (size_t)R0 * 128 + col) = o;
            }
            if (R1 < N_NODES) {
                __half2 o = __floats2half2_rn(c[mf][nb][2] * d1, c[mf][nb][3] * d1);
                *(__half2*)(hs + (size_t)R1 * 128 + col) = o;
            }
        }
    }
}

// ---------------------------------------------------------------------------
// Aggregate + finalize (fused, batched): one warp per dst node, lane = 4-dim
// chunk. hs rows are pre-scaled by dinv[src]; indices read as int4.
// out[n] = dinv[n] * (sum_e hs[src_e] + hs[n]) + b   (+ ReLU)
// Per-8-edge iteration: 2 idx LDG.128 + 8 gathers (was 24 LDGs).
// ---------------------------------------------------------------------------
__device__ __forceinline__ float4 h4tof4(uint2 v) {
    float2 lo = __half22float2(*(const __half2*)&v.x);
    float2 hi = __half22float2(*(const __half2*)&v.y);
    return make_float4(lo.x, lo.y, hi.x, hi.y);
}
__device__ __forceinline__ float4 f4add(float4 a, float4 b) {
    return make_float4(a.x + b.x, a.y + b.y, a.z + b.z, a.w + b.w);
}

__global__ __launch_bounds__(256)
void k_aggregate(const __half* __restrict__ hsA, const __half* __restrict__ hsB,
                 const float* __restrict__ b,
                 float* __restrict__ outA, float* __restrict__ outB, int do_relu) {
    int gnode = blockIdx.x * (blockDim.x >> 5) + (threadIdx.x >> 5);
    if (gnode >= 2 * N_NODES) return;
    int gph  = (gnode >= N_NODES) ? 1 : 0;
    int node = gnode - gph * N_NODES;
    int lane = threadIdx.x & 31;

    const int*   offs = g_offs + gph * (N_NODES + 1);
    const int*   csr  = g_csr  + gph * N_EDGES;
    const uint2* hs2  = (const uint2*)(gph ? hsB : hsA);
    float* out = gph ? outB : outA;

    int beg = __ldg(offs + node);
    int end = __ldg(offs + node + 1);
    float dd = __ldg(g_dinv + gnode);

    float4 a0 = h4tof4(__ldg(hs2 + (size_t)node * 32 + lane));  // self loop
    float4 a1 = make_float4(0.f, 0.f, 0.f, 0.f);
    float4 a2 = a1, a3 = a1, a4 = a1, a5 = a1, a6 = a1, a7 = a1;

    int e = beg;
    // peel to 16-byte alignment for int4 index loads
    while (e < end && (e & 3)) {
        int s = __ldg(csr + e);
        a1 = f4add(a1, h4tof4(__ldg(hs2 + (size_t)s * 32 + lane)));
        e++;
    }
    for (; e + 8 <= end; e += 8) {
        int4 sa = __ldg((const int4*)(csr + e));
        int4 sb = __ldg((const int4*)(csr + e + 4));
        uint2 v0 = __ldg(hs2 + (size_t)sa.x * 32 + lane);
        uint2 v1 = __ldg(hs2 + (size_t)sa.y * 32 + lane);
        uint2 v2 = __ldg(hs2 + (size_t)sa.z * 32 + lane);
        uint2 v3 = __ldg(hs2 + (size_t)sa.w * 32 + lane);
        uint2 v4 = __ldg(hs2 + (size_t)sb.x * 32 + lane);
        uint2 v5 = __ldg(hs2 + (size_t)sb.y * 32 + lane);
        uint2 v6 = __ldg(hs2 + (size_t)sb.z * 32 + lane);
        uint2 v7 = __ldg(hs2 + (size_t)sb.w * 32 + lane);
        a0 = f4add(a0, h4tof4(v0));  a1 = f4add(a1, h4tof4(v1));
        a2 = f4add(a2, h4tof4(v2));  a3 = f4add(a3, h4tof4(v3));
        a4 = f4add(a4, h4tof4(v4));  a5 = f4add(a5, h4tof4(v5));
        a6 = f4add(a6, h4tof4(v6));  a7 = f4add(a7, h4tof4(v7));
    }
    if (e + 4 <= end) {
        int4 sa = __ldg((const int4*)(csr + e));
        uint2 v0 = __ldg(hs2 + (size_t)sa.x * 32 + lane);
        uint2 v1 = __ldg(hs2 + (size_t)sa.y * 32 + lane);
        uint2 v2 = __ldg(hs2 + (size_t)sa.z * 32 + lane);
        uint2 v3 = __ldg(hs2 + (size_t)sa.w * 32 + lane);
        a0 = f4add(a0, h4tof4(v0));  a1 = f4add(a1, h4tof4(v1));
        a2 = f4add(a2, h4tof4(v2));  a3 = f4add(a3, h4tof4(v3));
        e += 4;
    }
    for (; e < end; e++) {
        int s = __ldg(csr + e);
        a0 = f4add(a0, h4tof4(__ldg(hs2 + (size_t)s * 32 + lane)));
    }
    float4 acc = f4add(f4add(f4add(a0, a1), f4add(a2, a3)),
                       f4add(f4add(a4, a5), f4add(a6, a7)));

    float4 bb = __ldg(((const float4*)b) + lane);
    float4 o;
    o.x = fmaf(acc.x, dd, bb.x);
    o.y = fmaf(acc.y, dd, bb.y);
    o.z = fmaf(acc.z, dd, bb.z);
    o.w = fmaf(acc.w, dd, bb.w);
    if (do_relu) {
        o.x = fmaxf(o.x, 0.f); o.y = fmaxf(o.y, 0.f);
        o.z = fmaxf(o.z, 0.f); o.w = fmaxf(o.w, 0.f);
    }
    ((float4*)out)[(size_t)node * 32 + lane] = o;
}

// ---------------------------------------------------------------------------
// Launch. k_gemm_tf32 (layer 1) stays at launch index 3 for the ncu window;
// it needs only g_cnt (ready after k_count2 at index 2).
// ---------------------------------------------------------------------------
extern "C" void kernel_launch(void* const* d_in, const int* in_sizes, int n_in,
                              void* d_out, int out_size) {
    const float* x1  = (const float*)d_in[0];
    const int*   ei1 = (const int*)  d_in[1];
    const float* x2  = (const float*)d_in[2];
    const int*   ei2 = (const int*)  d_in[3];
    const float* W0  = (const float*)d_in[4];
    const float* b0  = (const float*)d_in[5];
    const float* W1  = (const float*)d_in[6];
    const float* b1  = (const float*)d_in[7];
    float* out = (float*)d_out;

    const int* src1 = ei1;
    const int* dst1 = ei1 + N_EDGES;
    const int* src2 = ei2;
    const int* dst2 = ei2 + N_EDGES;

    float *h1, *h2;
    __half *hsA, *hsB;
    uint4* Bq;
    int* cnt;
    cudaGetSymbolAddress((void**)&hsA, g_hsA);
    cudaGetSymbolAddress((void**)&hsB, g_hsB);
    cudaGetSymbolAddress((void**)&h1,  g_h1);
    cudaGetSymbolAddress((void**)&h2,  g_h2);
    cudaGetSymbolAddress((void**)&Bq,  g_Bq);
    cudaGetSymbolAddress((void**)&cnt, g_cnt);

    k_splitw<<<32, 256>>>(W0, W1);                              // 0
    k_zero_cnt<<<(2 * N_NODES + 255) / 256, 256>>>();           // 1
    k_count2<<<2048, 256>>>(dst1, dst2);                        // 2
    k_gemm_tf32<<<2 * NBLK, 256>>>(x1, x2, Bq, cnt, hsA, hsB);  // 3  (ncu window)
    k_blocksum<<<N_TILES, TILE>>>();                            // 4
    k_scanbase<<<1, 256>>>();                                   // 5
    k_offsets<<<N_TILES, TILE>>>();                             // 6
    k_fill2<<<2048, 256>>>(src1, dst1, src2, dst2);             // 7

    const int AGG_GRID = (2 * N_NODES * 32 + 255) / 256;

    k_aggregate<<<AGG_GRID, 256>>>(hsA, hsB, b0, h1, h2, 1);
    k_gemm_tf32<<<2 * NBLK, 256>>>(h1, h2, Bq + 4096, cnt, hsA, hsB);
    k_aggregate<<<AGG_GRID, 256>>>(hsA, hsB, b1, out, out + (size_t)N_NODES * DIM, 0);
}

// round 13
// speedup vs baseline: 1.1955x; 1.1955x over previous
#include <cuda_runtime.h>
#include <cuda_fp16.h>
#include <cuda_bf16.h>

#define N_NODES 50000
#define DIM     128
#define N_EDGES 800000
#define TILE    512
#define TILES_PER_G 98          // ceil(50000/512)
#define N_TILES (2 * TILES_PER_G)
#define GM      128             // GEMM block M
#define NBLK    ((N_NODES + GM - 1) / GM)   // 391

// ---------------------------------------------------------------------------
// Scratch (device globals — no allocation allowed in kernel_launch)
// ---------------------------------------------------------------------------
__device__ int    g_cnt [2 * N_NODES];
__device__ int    g_offs[2 * (N_NODES + 1)];
__device__ int    g_cur [2 * N_NODES];
__device__ int    g_csr [2 * N_EDGES];
__device__ float  g_dinv[2 * N_NODES];
__device__ __half g_hsA [N_NODES * DIM];     // (x @ W) * dinv[row]  (fp16), graph 1
__device__ __half g_hsB [N_NODES * DIM];     // graph 2
__device__ float  g_h1  [N_NODES * DIM];     // hidden activations graph 1
__device__ float  g_h2  [N_NODES * DIM];     // graph 2
__device__ int    g_tilesum [N_TILES];
__device__ int    g_tilebase[N_TILES];
// B fragments, nb-paired: [layer][kc(4)][ks(4)][wnh(2)][nbp(4)][g(8)][l4(4)]
__device__ uint4  g_Bq[2 * 4096];

// ---------------------------------------------------------------------------
// tf32 helpers
// ---------------------------------------------------------------------------
__device__ __forceinline__ unsigned f2tf(float f) {
    unsigned r;
    asm("cvt.rna.tf32.f32 %0, %1;" : "=r"(r) : "f"(f));
    return r;
}

__device__ __forceinline__ void mma8(float c[4], const unsigned a[4],
                                     unsigned b0, unsigned b1) {
    asm volatile(
        "mma.sync.aligned.m16n8k8.row.col.f32.tf32.tf32.f32 "
        "{%0,%1,%2,%3}, {%4,%5,%6,%7}, {%8,%9}, {%0,%1,%2,%3};"
        : "+f"(c[0]), "+f"(c[1]), "+f"(c[2]), "+f"(c[3])
        : "r"(a[0]), "r"(a[1]), "r"(a[2]), "r"(a[3]), "r"(b0), "r"(b1));
}

// ---------------------------------------------------------------------------
// W pre-pack (tf32-rounded, nb-paired fragments)
// ---------------------------------------------------------------------------
__global__ void k_splitw(const float* __restrict__ W0, const float* __restrict__ W1) {
    int i = blockIdx.x * blockDim.x + threadIdx.x;
    if (i >= 8192) return;
    const float* W = (i < 4096) ? W0 : W1;
    int j   = i & 4095;
    int l4  = j & 3;
    int g   = (j >> 2) & 7;
    int nbp = (j >> 5) & 3;
    int wnh = (j >> 7) & 1;
    int ks  = (j >> 8) & 3;
    int kc  = j >> 10;
    int k0  = kc * 32 + ks * 8;
    int n0  = wnh * 64 + (2 * nbp) * 8 + g;
    int n1  = n0 + 8;
    uint4 v;
    v.x = f2tf(W[(k0 + l4)     * 128 + n0]);
    v.y = f2tf(W[(k0 + l4 + 4) * 128 + n0]);
    v.z = f2tf(W[(k0 + l4)     * 128 + n1]);
    v.w = f2tf(W[(k0 + l4 + 4) * 128 + n1]);
    g_Bq[i] = v;
}

// ---------------------------------------------------------------------------
// CSR build
// ---------------------------------------------------------------------------
__global__ void k_zero_cnt() {
    int i = blockIdx.x * blockDim.x + threadIdx.x;
    if (i < 2 * N_NODES) g_cnt[i] = 0;
}

// Count in-degrees, both graphs, int4-vectorized edge reads (N_EDGES % 4 == 0).
__global__ void k_count2(const int* __restrict__ dst1, const int* __restrict__ dst2) {
    const int Q = N_EDGES / 4;
    int i = blockIdx.x * blockDim.x + threadIdx.x;
    int stride = gridDim.x * blockDim.x;
    for (; i < 2 * Q; i += stride) {
        int4 d;
        int base;
        if (i < Q) { d = __ldg((const int4*)dst1 + i); base = 0; }
        else       { d = __ldg((const int4*)dst2 + (i - Q)); base = N_NODES; }
        atomicAdd(&g_cnt[base + d.x], 1);
        atomicAdd(&g_cnt[base + d.y], 1);
        atomicAdd(&g_cnt[base + d.z], 1);
        atomicAdd(&g_cnt[base + d.w], 1);
    }
}

__global__ __launch_bounds__(TILE)
void k_blocksum() {
    int g  = blockIdx.x / TILES_PER_G;
    int lt = blockIdx.x % TILES_PER_G;
    int li = lt * TILE + threadIdx.x;
    int c = (li < N_NODES) ? g_cnt[g * N_NODES + li] : 0;

    int lane = threadIdx.x & 31, w = threadIdx.x >> 5;
    for (int o = 16; o > 0; o >>= 1) c += __shfl_down_sync(~0u, c, o);
    __shared__ int ws[TILE / 32];
    if (lane == 0) ws[w] = c;
    __syncthreads();
    if (threadIdx.x == 0) {
        int s = 0;
#pragma unroll
        for (int i = 0; i < TILE / 32; i++) s += ws[i];
        g_tilesum[blockIdx.x] = s;
    }
}

__global__ __launch_bounds__(256)
void k_scanbase() {
    __shared__ int s[N_TILES];
    if (threadIdx.x < N_TILES) s[threadIdx.x] = g_tilesum[threadIdx.x];
    __syncthreads();
    if (threadIdx.x < 2) {
        int g = threadIdx.x;
        int run = 0;
        for (int t = 0; t < TILES_PER_G; t++) {
            g_tilebase[g * TILES_PER_G + t] = run;
            run += s[g * TILES_PER_G + t];
        }
        g_offs[g * (N_NODES + 1) + N_NODES] = run;
    }
}

__global__ __launch_bounds__(TILE)
void k_offsets() {
    int g  = blockIdx.x / TILES_PER_G;
    int lt = blockIdx.x % TILES_PER_G;
    int li = lt * TILE + threadIdx.x;
    int c = (li < N_NODES) ? g_cnt[g * N_NODES + li] : 0;

    int lane = threadIdx.x & 31, w = threadIdx.x >> 5;
    int v = c;
#pragma unroll
    for (int o = 1; o < 32; o <<= 1) {
        int t = __shfl_up_sync(~0u, v, o);
        if (lane >= o) v += t;
    }
    __shared__ int ws[TILE / 32];
    if (lane == 31) ws[w] = v;
    __syncthreads();
    if (w == 0 && lane < TILE / 32) {
        int s = ws[lane];
#pragma unroll
        for (int o = 1; o < TILE / 32; o <<= 1) {
            int t = __shfl_up_sync(0xffff, s, o);
            if (lane >= o) s += t;
        }
        ws[lane] = s;
    }
    __syncthreads();
    int excl = v - c + (w > 0 ? ws[w - 1] : 0);

    if (li < N_NODES) {
        int off = g_tilebase[blockIdx.x] + excl;
        g_offs[g * (N_NODES + 1) + li] = off;
        g_cur [g * N_NODES + li] = off;
        g_dinv[g * N_NODES + li] = rsqrtf(1.0f + (float)c);
    }
}

// Fill CSR, both graphs, int4-vectorized edge reads.
__global__ void k_fill2(const int* __restrict__ src1, const int* __restrict__ dst1,
                        const int* __restrict__ src2, const int* __restrict__ dst2) {
    const int Q = N_EDGES / 4;
    int i = blockIdx.x * blockDim.x + threadIdx.x;
    int stride = gridDim.x * blockDim.x;
    for (; i < 2 * Q; i += stride) {
        int4 s, d;
        int nbase, ebase;
        if (i < Q) {
            s = __ldg((const int4*)src1 + i);
            d = __ldg((const int4*)dst1 + i);
            nbase = 0; ebase = 0;
        } else {
            s = __ldg((const int4*)src2 + (i - Q));
            d = __ldg((const int4*)dst2 + (i - Q));
            nbase = N_NODES; ebase = N_EDGES;
        }
        g_csr[ebase + atomicAdd(&g_cur[nbase + d.x], 1)] = s.x;
        g_csr[ebase + atomicAdd(&g_cur[nbase + d.y], 1)] = s.y;
        g_csr[ebase + atomicAdd(&g_cur[nbase + d.z], 1)] = s.z;
        g_csr[ebase + atomicAdd(&g_cur[nbase + d.w], 1)] = s.w;
    }
}

// ---------------------------------------------------------------------------
// GEMM (single-pass TF32, fragment-native A, nb-paired B). Unchanged from R12.
// hs[m][:] = (x[m][:] @ W) * rsqrt(1+cnt[m]). fp16 output.
// ---------------------------------------------------------------------------
__global__ __launch_bounds__(256, 2)
void k_gemm_tf32(const float* __restrict__ xA, const float* __restrict__ xB,
                 const uint4* __restrict__ Bq, const int* __restrict__ cntAB,
                 __half* __restrict__ hsA, __half* __restrict__ hsB) {
    __shared__ uint4 xs[8 * 4 * 32];
    __shared__ uint4 Bs[1024];

    const int tid  = threadIdx.x;
    const int lane = tid & 31;
    const int wid  = tid >> 5;
    const int g    = lane >> 2;
    const int l4   = lane & 3;
    const int wm   = (wid & 3) * 32;
    const int wnh  = wid >> 2;
    const int wn   = wnh * 64;

    const int gph  = (blockIdx.x >= NBLK) ? 1 : 0;
    const int m0   = (blockIdx.x - gph * NBLK) * GM;
    const float* x = gph ? xB : xA;
    __half* hs     = gph ? hsB : hsA;
    const int* cnt = cntAB + gph * N_NODES;

    float c[2][8][4];
#pragma unroll
    for (int mf = 0; mf < 2; mf++)
#pragma unroll
        for (int nb = 0; nb < 8; nb++)
#pragma unroll
            for (int q = 0; q < 4; q++) c[mf][nb][q] = 0.0f;

    for (int kc = 0; kc < 4; kc++) {
#pragma unroll
        for (int j = 0; j < 4; j++)
            Bs[tid + j * 256] = __ldg(Bq + kc * 1024 + tid + j * 256);

        unsigned* xsu = (unsigned*)xs;
#pragma unroll
        for (int i = 0; i < 4; i++) {
            int f  = i * 256 + tid;
            int r  = f >> 3;
            int cc = f & 7;
            int R  = m0 + r;
            float4 v = make_float4(0.f, 0.f, 0.f, 0.f);
            if (R < N_NODES)
                v = __ldg((const float4*)x + (size_t)R * 32 + kc * 8 + cc);
            int rr   = r & 15;
            int mb   = r >> 4;
            int g2   = rr & 7;
            int slot = (rr >> 3) + (cc & 1) * 2;
            int ks   = cc >> 1;
            int base = (mb * 4 + ks) * 32;
            unsigned t0 = f2tf(v.x), t1 = f2tf(v.y), t2 = f2tf(v.z), t3 = f2tf(v.w);
            xsu[((base + ((g2 * 4 + 0 + ks * 2) & 31)) << 2) + slot] = t0;
            xsu[((base + ((g2 * 4 + 1 + ks * 2) & 31)) << 2) + slot] = t1;
            xsu[((base + ((g2 * 4 + 2 + ks * 2) & 31)) << 2) + slot] = t2;
            xsu[((base + ((g2 * 4 + 3 + ks * 2) & 31)) << 2) + slot] = t3;
        }
        __syncthreads();

#pragma unroll
        for (int ks = 0; ks < 4; ks++) {
            unsigned afrag[2][4];
#pragma unroll
            for (int mf = 0; mf < 2; mf++) {
                int mb = (wid & 3) * 2 + mf;
                uint4 a = xs[(mb * 4 + ks) * 32 + ((lane + ks * 2) & 31)];
                afrag[mf][0] = a.x; afrag[mf][1] = a.y;
                afrag[mf][2] = a.z; afrag[mf][3] = a.w;
            }
#pragma unroll
            for (int nbp = 0; nbp < 4; nbp++) {
                uint4 bb = Bs[((ks * 2 + wnh) * 4 + nbp) * 32 + g * 4 + l4];
#pragma unroll
                for (int mf = 0; mf < 2; mf++) {
                    mma8(c[mf][2 * nbp],     afrag[mf], bb.x, bb.y);
                    mma8(c[mf][2 * nbp + 1], afrag[mf], bb.z, bb.w);
                }
            }
        }
        __syncthreads();
    }

#pragma unroll
    for (int mf = 0; mf < 2; mf++) {
        int R0 = m0 + wm + mf * 16 + g;
        int R1 = R0 + 8;
        float d0 = (R0 < N_NODES) ? rsqrtf(1.0f + (float)__ldg(cnt + R0)) : 0.f;
        float d1 = (R1 < N_NODES) ? rsqrtf(1.0f + (float)__ldg(cnt + R1)) : 0.f;
#pragma unroll
        for (int nb = 0; nb < 8; nb++) {
            int col = wn + nb * 8 + 2 * l4;
            if (R0 < N_NODES) {
                __half2 o = __floats2half2_rn(c[mf][nb][0] * d0, c[mf][nb][1] * d0);
                *(__half2*)(hs + (size_t)R0 * 128 + col) = o;
            }
            if (R1 < N_NODES) {
                __half2 o = __floats2half2_rn(c[mf][nb][2] * d1, c[mf][nb][3] * d1);
                *(__half2*)(hs + (size_t)R1 * 128 + col) = o;
            }
        }
    }
}

// ---------------------------------------------------------------------------
// Aggregate + finalize v2: HALF-WARP per node (16 lanes x uint4 = 256B row).
// Doubles node-level concurrency per resident warp slot vs warp-per-node.
// out[n] = dinv[n] * (sum_e hs[src_e] + hs[n]) + b   (+ ReLU)
// 4 independent accumulator chains (8 fp32 dims per lane).
// ---------------------------------------------------------------------------
__device__ __forceinline__ float4 h4tof4u(unsigned lo, unsigned hi) {
    float2 a = __half22float2(*(const __half2*)&lo);
    float2 b = __half22float2(*(const __half2*)&hi);
    return make_float4(a.x, a.y, b.x, b.y);
}
__device__ __forceinline__ void acc8(float4& L, float4& H, uint4 v) {
    float4 l = h4tof4u(v.x, v.y);
    float4 h = h4tof4u(v.z, v.w);
    L.x += l.x; L.y += l.y; L.z += l.z; L.w += l.w;
    H.x += h.x; H.y += h.y; H.z += h.z; H.w += h.w;
}
__device__ __forceinline__ float4 f4add(float4 a, float4 b) {
    return make_float4(a.x + b.x, a.y + b.y, a.z + b.z, a.w + b.w);
}

__global__ __launch_bounds__(256)
void k_aggregate(const __half* __restrict__ hsA, const __half* __restrict__ hsB,
                 const float* __restrict__ b,
                 float* __restrict__ outA, float* __restrict__ outB, int do_relu) {
    int hid = blockIdx.x * 16 + (threadIdx.x >> 4);   // half-warp id = node id
    if (hid >= 2 * N_NODES) return;
    int gph  = (hid >= N_NODES) ? 1 : 0;
    int node = hid - gph * N_NODES;
    int h    = threadIdx.x & 15;                      // 16B chunk of the row

    const int*   offs = g_offs + gph * (N_NODES + 1);
    const int*   csr  = g_csr  + gph * N_EDGES;
    const uint4* hs4  = (const uint4*)(gph ? hsB : hsA);
    float* out = gph ? outB : outA;

    int beg = __ldg(offs + node);
    int end = __ldg(offs + node + 1);
    float dd = __ldg(g_dinv + hid);

    float4 L0 = make_float4(0.f, 0.f, 0.f, 0.f), H0 = L0;
    float4 L1 = L0, H1 = L0, L2 = L0, H2 = L0, L3 = L0, H3 = L0;
    acc8(L0, H0, __ldg(hs4 + (size_t)node * 16 + h));   // self loop (pre-scaled)

    int e = beg;
    while (e < end && (e & 3)) {                        // peel to int4 alignment
        int s = __ldg(csr + e);
        acc8(L1, H1, __ldg(hs4 + (size_t)s * 16 + h));
        e++;
    }
    for (; e + 4 <= end; e += 4) {
        int4 s = __ldg((const int4*)(csr + e));
        uint4 v0 = __ldg(hs4 + (size_t)s.x * 16 + h);
        uint4 v1 = __ldg(hs4 + (size_t)s.y * 16 + h);
        uint4 v2 = __ldg(hs4 + (size_t)s.z * 16 + h);
        uint4 v3 = __ldg(hs4 + (size_t)s.w * 16 + h);
        acc8(L0, H0, v0);
        acc8(L1, H1, v1);
        acc8(L2, H2, v2);
        acc8(L3, H3, v3);
    }
    for (; e < end; e++) {
        int s = __ldg(csr + e);
        acc8(L0, H0, __ldg(hs4 + (size_t)s * 16 + h));
    }
    float4 L = f4add(f4add(L0, L1), f4add(L2, L3));
    float4 H = f4add(f4add(H0, H1), f4add(H2, H3));

    float4 b0 = __ldg(((const float4*)b) + h * 2);
    float4 b1 = __ldg(((const float4*)b) + h * 2 + 1);
    float4 o0, o1;
    o0.x = fmaf(L.x, dd, b0.x); o0.y = fmaf(L.y, dd, b0.y);
    o0.z = fmaf(L.z, dd, b0.z); o0.w = fmaf(L.w, dd, b0.w);
    o1.x = fmaf(H.x, dd, b1.x); o1.y = fmaf(H.y, dd, b1.y);
    o1.z = fmaf(H.z, dd, b1.z); o1.w = fmaf(H.w, dd, b1.w);
    if (do_relu) {
        o0.x = fmaxf(o0.x, 0.f); o0.y = fmaxf(o0.y, 0.f);
        o0.z = fmaxf(o0.z, 0.f); o0.w = fmaxf(o0.w, 0.f);
        o1.x = fmaxf(o1.x, 0.f); o1.y = fmaxf(o1.y, 0.f);
        o1.z = fmaxf(o1.z, 0.f); o1.w = fmaxf(o1.w, 0.f);
    }
    ((float4*)out)[(size_t)node * 32 + h * 2]     = o0;
    ((float4*)out)[(size_t)node * 32 + h * 2 + 1] = o1;
}

// ---------------------------------------------------------------------------
// Launch. k_gemm_tf32 (layer 1) stays at launch index 3 for the ncu window.
// ---------------------------------------------------------------------------
extern "C" void kernel_launch(void* const* d_in, const int* in_sizes, int n_in,
                              void* d_out, int out_size) {
    const float* x1  = (const float*)d_in[0];
    const int*   ei1 = (const int*)  d_in[1];
    const float* x2  = (const float*)d_in[2];
    const int*   ei2 = (const int*)  d_in[3];
    const float* W0  = (const float*)d_in[4];
    const float* b0  = (const float*)d_in[5];
    const float* W1  = (const float*)d_in[6];
    const float* b1  = (const float*)d_in[7];
    float* out = (float*)d_out;

    const int* src1 = ei1;
    const int* dst1 = ei1 + N_EDGES;
    const int* src2 = ei2;
    const int* dst2 = ei2 + N_EDGES;

    float *h1, *h2;
    __half *hsA, *hsB;
    uint4* Bq;
    int* cnt;
    cudaGetSymbolAddress((void**)&hsA, g_hsA);
    cudaGetSymbolAddress((void**)&hsB, g_hsB);
    cudaGetSymbolAddress((void**)&h1,  g_h1);
    cudaGetSymbolAddress((void**)&h2,  g_h2);
    cudaGetSymbolAddress((void**)&Bq,  g_Bq);
    cudaGetSymbolAddress((void**)&cnt, g_cnt);

    k_splitw<<<32, 256>>>(W0, W1);                              // 0
    k_zero_cnt<<<(2 * N_NODES + 255) / 256, 256>>>();           // 1
    k_count2<<<1024, 256>>>(dst1, dst2);                        // 2
    k_gemm_tf32<<<2 * NBLK, 256>>>(x1, x2, Bq, cnt, hsA, hsB);  // 3  (ncu window)
    k_blocksum<<<N_TILES, TILE>>>();                            // 4
    k_scanbase<<<1, 256>>>();                                   // 5
    k_offsets<<<N_TILES, TILE>>>();                             // 6
    k_fill2<<<1024, 256>>>(src1, dst1, src2, dst2);             // 7

    const int AGG_GRID = (2 * N_NODES + 15) / 16;               // 6250 blocks

    k_aggregate<<<AGG_GRID, 256>>>(hsA, hsB, b0, h1, h2, 1);
    k_gemm_tf32<<<2 * NBLK, 256>>>(h1, h2, Bq + 4096, cnt, hsA, hsB);
    k_aggregate<<<AGG_GRID, 256>>>(hsA, hsB, b1, out, out + (size_t)N_NODES * DIM, 0);
}

// round 14
// speedup vs baseline: 1.4365x; 1.2016x over previous
#include <cuda_runtime.h>
#include <cuda_fp16.h>
#include <cuda_bf16.h>

#define N_NODES 50000
#define DIM     128
#define N_EDGES 800000
#define TILE    512
#define TILES_PER_G 98          // ceil(50000/512)
#define N_TILES (2 * TILES_PER_G)
#define GM      128             // GEMM block M
#define NBLK    ((N_NODES + GM - 1) / GM)   // 391

// ---------------------------------------------------------------------------
// Scratch (device globals — no allocation allowed in kernel_launch)
// ---------------------------------------------------------------------------
__device__ int    g_cnt [2 * N_NODES];
__device__ int    g_offs[2 * (N_NODES + 1)];
__device__ int    g_cur [2 * N_NODES];
__device__ int    g_csr [2 * N_EDGES];
__device__ float  g_dinv[2 * N_NODES];
__device__ __half g_hsA [N_NODES * DIM];     // (x @ W) * dinv[row]  (fp16), graph 1
__device__ __half g_hsB [N_NODES * DIM];     // graph 2
__device__ float  g_h1  [N_NODES * DIM];     // hidden activations graph 1
__device__ float  g_h2  [N_NODES * DIM];     // graph 2
__device__ int    g_tilesum [N_TILES];
__device__ int    g_tilebase[N_TILES];
// fp16 B fragments, nb-paired, m16n8k16:
// [layer][kc(4)][ks(2)][wnh(2)][nbp(4)][g(8)][l4(4)]
//   uint4 = {b0(nb), b1(nb), b0(nb+1), b1(nb+1)},  n = wnh*64 + nb*8 + g
//   b0 = half2{W[k0+l4*2][n],   W[k0+l4*2+1][n]},  k0 = kc*32 + ks*16
//   b1 = half2{W[k0+8+l4*2][n], W[k0+8+l4*2+1][n]}
__device__ uint4  g_Bq[2 * 2048];

// ---------------------------------------------------------------------------
// mma m16n8k16 fp16 -> fp32
// ---------------------------------------------------------------------------
__device__ __forceinline__ void mma16(float c[4], const unsigned a[4],
                                      unsigned b0, unsigned b1) {
    asm volatile(
        "mma.sync.aligned.m16n8k16.row.col.f32.f16.f16.f32 "
        "{%0,%1,%2,%3}, {%4,%5,%6,%7}, {%8,%9}, {%0,%1,%2,%3};"
        : "+f"(c[0]), "+f"(c[1]), "+f"(c[2]), "+f"(c[3])
        : "r"(a[0]), "r"(a[1]), "r"(a[2]), "r"(a[3]), "r"(b0), "r"(b1));
}

__device__ __forceinline__ unsigned pack_h2(float x, float y) {
    __half2 h = __floats2half2_rn(x, y);
    return *(unsigned*)&h;
}

// ---------------------------------------------------------------------------
// W pre-pack (fp16, m16n8k16 fragment-native, nb-paired)
// ---------------------------------------------------------------------------
__global__ void k_packw(const float* __restrict__ W0, const float* __restrict__ W1) {
    int i = blockIdx.x * blockDim.x + threadIdx.x;
    if (i >= 4096) return;
    const float* W = (i < 2048) ? W0 : W1;
    int j   = i & 2047;
    int l4  = j & 3;
    int g   = (j >> 2) & 7;
    int nbp = (j >> 5) & 3;
    int wnh = (j >> 7) & 1;
    int ks  = (j >> 8) & 1;
    int kc  = j >> 9;
    int k0  = kc * 32 + ks * 16;
    int n0  = wnh * 64 + nbp * 16 + g;
    int n1  = n0 + 8;
    uint4 v;
    v.x = pack_h2(W[(k0 + l4 * 2)     * 128 + n0], W[(k0 + l4 * 2 + 1) * 128 + n0]);
    v.y = pack_h2(W[(k0 + 8 + l4 * 2) * 128 + n0], W[(k0 + 9 + l4 * 2) * 128 + n0]);
    v.z = pack_h2(W[(k0 + l4 * 2)     * 128 + n1], W[(k0 + l4 * 2 + 1) * 128 + n1]);
    v.w = pack_h2(W[(k0 + 8 + l4 * 2) * 128 + n1], W[(k0 + 9 + l4 * 2) * 128 + n1]);
    g_Bq[i] = v;
}

// ---------------------------------------------------------------------------
// CSR build
// ---------------------------------------------------------------------------
__global__ void k_zero_cnt() {
    int i = blockIdx.x * blockDim.x + threadIdx.x;
    if (i < 2 * N_NODES) g_cnt[i] = 0;
}

__global__ void k_count2(const int* __restrict__ dst1, const int* __restrict__ dst2) {
    const int Q = N_EDGES / 4;
    int i = blockIdx.x * blockDim.x + threadIdx.x;
    int stride = gridDim.x * blockDim.x;
    for (; i < 2 * Q; i += stride) {
        int4 d;
        int base;
        if (i < Q) { d = __ldg((const int4*)dst1 + i); base = 0; }
        else       { d = __ldg((const int4*)dst2 + (i - Q)); base = N_NODES; }
        atomicAdd(&g_cnt[base + d.x], 1);
        atomicAdd(&g_cnt[base + d.y], 1);
        atomicAdd(&g_cnt[base + d.z], 1);
        atomicAdd(&g_cnt[base + d.w], 1);
    }
}

__global__ __launch_bounds__(TILE)
void k_blocksum() {
    int g  = blockIdx.x / TILES_PER_G;
    int lt = blockIdx.x % TILES_PER_G;
    int li = lt * TILE + threadIdx.x;
    int c = (li < N_NODES) ? g_cnt[g * N_NODES + li] : 0;

    int lane = threadIdx.x & 31, w = threadIdx.x >> 5;
    for (int o = 16; o > 0; o >>= 1) c += __shfl_down_sync(~0u, c, o);
    __shared__ int ws[TILE / 32];
    if (lane == 0) ws[w] = c;
    __syncthreads();
    if (threadIdx.x == 0) {
        int s = 0;
#pragma unroll
        for (int i = 0; i < TILE / 32; i++) s += ws[i];
        g_tilesum[blockIdx.x] = s;
    }
}

__global__ __launch_bounds__(256)
void k_scanbase() {
    __shared__ int s[N_TILES];
    if (threadIdx.x < N_TILES) s[threadIdx.x] = g_tilesum[threadIdx.x];
    __syncthreads();
    if (threadIdx.x < 2) {
        int g = threadIdx.x;
        int run = 0;
        for (int t = 0; t < TILES_PER_G; t++) {
            g_tilebase[g * TILES_PER_G + t] = run;
            run += s[g * TILES_PER_G + t];
        }
        g_offs[g * (N_NODES + 1) + N_NODES] = run;
    }
}

__global__ __launch_bounds__(TILE)
void k_offsets() {
    int g  = blockIdx.x / TILES_PER_G;
    int lt = blockIdx.x % TILES_PER_G;
    int li = lt * TILE + threadIdx.x;
    int c = (li < N_NODES) ? g_cnt[g * N_NODES + li] : 0;

    int lane = threadIdx.x & 31, w = threadIdx.x >> 5;
    int v = c;
#pragma unroll
    for (int o = 1; o < 32; o <<= 1) {
        int t = __shfl_up_sync(~0u, v, o);
        if (lane >= o) v += t;
    }
    __shared__ int ws[TILE / 32];
    if (lane == 31) ws[w] = v;
    __syncthreads();
    if (w == 0 && lane < TILE / 32) {
        int s = ws[lane];
#pragma unroll
        for (int o = 1; o < TILE / 32; o <<= 1) {
            int t = __shfl_up_sync(0xffff, s, o);
            if (lane >= o) s += t;
        }
        ws[lane] = s;
    }
    __syncthreads();
    int excl = v - c + (w > 0 ? ws[w - 1] : 0);

    if (li < N_NODES) {
        int off = g_tilebase[blockIdx.x] + excl;
        g_offs[g * (N_NODES + 1) + li] = off;
        g_cur [g * N_NODES + li] = off;
        g_dinv[g * N_NODES + li] = rsqrtf(1.0f + (float)c);
    }
}

__global__ void k_fill2(const int* __restrict__ src1, const int* __restrict__ dst1,
                        const int* __restrict__ src2, const int* __restrict__ dst2) {
    const int Q = N_EDGES / 4;
    int i = blockIdx.x * blockDim.x + threadIdx.x;
    int stride = gridDim.x * blockDim.x;
    for (; i < 2 * Q; i += stride) {
        int4 s, d;
        int nbase, ebase;
        if (i < Q) {
            s = __ldg((const int4*)src1 + i);
            d = __ldg((const int4*)dst1 + i);
            nbase = 0; ebase = 0;
        } else {
            s = __ldg((const int4*)src2 + (i - Q));
            d = __ldg((const int4*)dst2 + (i - Q));
            nbase = N_NODES; ebase = N_EDGES;
        }
        g_csr[ebase + atomicAdd(&g_cur[nbase + d.x], 1)] = s.x;
        g_csr[ebase + atomicAdd(&g_cur[nbase + d.y], 1)] = s.y;
        g_csr[ebase + atomicAdd(&g_cur[nbase + d.z], 1)] = s.z;
        g_csr[ebase + atomicAdd(&g_cur[nbase + d.w], 1)] = s.w;
    }
}

// ---------------------------------------------------------------------------
// GEMM (fp16 HMMA m16n8k16): hs[m][:] = (x[m][:] @ W) * rsqrt(1+cnt[m]).
// A fragments loaded DIRECTLY from gmem (float2 -> half2), no A smem.
// B: all 4 k-chunks staged in smem once (32KB), single __syncthreads.
// Block 128(M) x 128(N), 8 warps (4M x 2N), warp tile 32x64. fp16 output.
// ---------------------------------------------------------------------------
__global__ __launch_bounds__(256, 2)
void k_gemm_h16(const float* __restrict__ xA, const float* __restrict__ xB,
                const uint4* __restrict__ Bq, const int* __restrict__ cntAB,
                __half* __restrict__ hsA, __half* __restrict__ hsB) {
    __shared__ uint4 Bs[2048];   // [kc][ks][wnh][nbp][lane]  (full K, 32KB)

    const int tid  = threadIdx.x;
    const int lane = tid & 31;
    const int wid  = tid >> 5;
    const int g    = lane >> 2;
    const int l4   = lane & 3;
    const int wm   = (wid & 3) * 32;
    const int wnh  = wid >> 2;
    const int wn   = wnh * 64;

    const int gph  = (blockIdx.x >= NBLK) ? 1 : 0;
    const int m0   = (blockIdx.x - gph * NBLK) * GM;
    const float* x = gph ? xB : xA;
    __half* hs     = gph ? hsB : hsA;
    const int* cnt = cntAB + gph * N_NODES;

    // Stage ALL of B (2048 uint4)
#pragma unroll
    for (int j = 0; j < 8; j++)
        Bs[tid + j * 256] = __ldg(Bq + tid + j * 256);
    __syncthreads();

    float c[2][8][4];
#pragma unroll
    for (int mf = 0; mf < 2; mf++)
#pragma unroll
        for (int nb = 0; nb < 8; nb++)
#pragma unroll
            for (int q = 0; q < 4; q++) c[mf][nb][q] = 0.0f;

    // Row indices for this thread's A fragments
    int R0 = m0 + wm + g;        // mf=0 rows: R0, R0+8
    int R1 = R0 + 16;            // mf=1 rows: R1, R1+8
    bool v00 = (R0      < N_NODES), v01 = (R0 + 8  < N_NODES);
    bool v10 = (R1      < N_NODES), v11 = (R1 + 8  < N_NODES);
    const float* p00 = x + (size_t)R0 * 128 + l4 * 2;
    const float* p01 = p00 + 8 * 128;
    const float* p10 = x + (size_t)R1 * 128 + l4 * 2;
    const float* p11 = p10 + 8 * 128;
    float2 z2 = make_float2(0.f, 0.f);

#pragma unroll
    for (int kc = 0; kc < 4; kc++) {
#pragma unroll
        for (int ks = 0; ks < 2; ks++) {
            int k0 = kc * 32 + ks * 16;
            // A fragments direct from gmem: 8 x LDG.64 -> 8 cvt
            float2 q00 = v00 ? __ldg((const float2*)(p00 + k0))     : z2;
            float2 q01 = v01 ? __ldg((const float2*)(p01 + k0))     : z2;
            float2 q02 = v00 ? __ldg((const float2*)(p00 + k0 + 8)) : z2;
            float2 q03 = v01 ? __ldg((const float2*)(p01 + k0 + 8)) : z2;
            float2 q10 = v10 ? __ldg((const float2*)(p10 + k0))     : z2;
            float2 q11 = v11 ? __ldg((const float2*)(p11 + k0))     : z2;
            float2 q12 = v10 ? __ldg((const float2*)(p10 + k0 + 8)) : z2;
            float2 q13 = v11 ? __ldg((const float2*)(p11 + k0 + 8)) : z2;
            unsigned a0[4], a1[4];
            a0[0] = pack_h2(q00.x, q00.y);
            a0[1] = pack_h2(q01.x, q01.y);
            a0[2] = pack_h2(q02.x, q02.y);
            a0[3] = pack_h2(q03.x, q03.y);
            a1[0] = pack_h2(q10.x, q10.y);
            a1[1] = pack_h2(q11.x, q11.y);
            a1[2] = pack_h2(q12.x, q12.y);
            a1[3] = pack_h2(q13.x, q13.y);
#pragma unroll
            for (int nbp = 0; nbp < 4; nbp++) {
                uint4 bb = Bs[(((kc * 2 + ks) * 2 + wnh) * 4 + nbp) * 32 + lane];
                mma16(c[0][2 * nbp],     a0, bb.x, bb.y);
                mma16(c[0][2 * nbp + 1], a0, bb.z, bb.w);
                mma16(c[1][2 * nbp],     a1, bb.x, bb.y);
                mma16(c[1][2 * nbp + 1], a1, bb.z, bb.w);
            }
        }
    }

    // Epilogue: scale by rsqrt(1+cnt[row]), store fp16
#pragma unroll
    for (int mf = 0; mf < 2; mf++) {
        int Ra = m0 + wm + mf * 16 + g;
        int Rb = Ra + 8;
        float d0 = (Ra < N_NODES) ? rsqrtf(1.0f + (float)__ldg(cnt + Ra)) : 0.f;
        float d1 = (Rb < N_NODES) ? rsqrtf(1.0f + (float)__ldg(cnt + Rb)) : 0.f;
#pragma unroll
        for (int nb = 0; nb < 8; nb++) {
            int col = wn + nb * 8 + 2 * l4;
            if (Ra < N_NODES) {
                __half2 o = __floats2half2_rn(c[mf][nb][0] * d0, c[mf][nb][1] * d0);
                *(__half2*)(hs + (size_t)Ra * 128 + col) = o;
            }
            if (Rb < N_NODES) {
                __half2 o = __floats2half2_rn(c[mf][nb][2] * d1, c[mf][nb][3] * d1);
                *(__half2*)(hs + (size_t)Rb * 128 + col) = o;
            }
        }
    }
}

// ---------------------------------------------------------------------------
// Aggregate + finalize v3: QUARTER-WARP per node (8 lanes x 2 uint4 = 256B).
// 4 independent node chains per warp slot. 2 accumulator chain-sets.
// out[n] = dinv[n] * (sum_e hs[src_e] + hs[n]) + b   (+ ReLU)
// ---------------------------------------------------------------------------
__device__ __forceinline__ float4 h4tof4u(unsigned lo, unsigned hi) {
    float2 a = __half22float2(*(const __half2*)&lo);
    float2 b = __half22float2(*(const __half2*)&hi);
    return make_float4(a.x, a.y, b.x, b.y);
}
__device__ __forceinline__ void acc2(float4& X, float4& Y, uint4 v) {
    float4 l = h4tof4u(v.x, v.y);
    float4 h = h4tof4u(v.z, v.w);
    X.x += l.x; X.y += l.y; X.z += l.z; X.w += l.w;
    Y.x += h.x; Y.y += h.y; Y.z += h.z; Y.w += h.w;
}
__device__ __forceinline__ float4 f4add(float4 a, float4 b) {
    return make_float4(a.x + b.x, a.y + b.y, a.z + b.z, a.w + b.w);
}

__global__ __launch_bounds__(128)
void k_aggregate(const __half* __restrict__ hsA, const __half* __restrict__ hsB,
                 const float* __restrict__ b,
                 float* __restrict__ outA, float* __restrict__ outB, int do_relu) {
    int qid = blockIdx.x * 16 + (threadIdx.x >> 3);   // quarter-warp id = node
    if (qid >= 2 * N_NODES) return;
    int gph  = (qid >= N_NODES) ? 1 : 0;
    int node = qid - gph * N_NODES;
    int h    = threadIdx.x & 7;                       // 32B chunk pair

    const int*   offs = g_offs + gph * (N_NODES + 1);
    const int*   csr  = g_csr  + gph * N_EDGES;
    const uint4* hs4  = (const uint4*)(gph ? hsB : hsA);
    float* out = gph ? outB : outA;

    int beg = __ldg(offs + node);
    int end = __ldg(offs + node + 1);
    float dd = __ldg(g_dinv + qid);

    // chain 0: A0..A3 (lo.lo, lo.hi, hi.lo, hi.hi); chain 1: B0..B3
    float4 A0 = make_float4(0.f, 0.f, 0.f, 0.f);
    float4 A1 = A0, A2 = A0, A3 = A0;
    float4 B0 = A0, B1 = A0, B2 = A0, B3 = A0;
    {   // self loop (row pre-scaled by dinv[node])
        uint4 vl = __ldg(hs4 + (size_t)node * 16 + h);
        uint4 vh = __ldg(hs4 + (size_t)node * 16 + 8 + h);
        acc2(A0, A1, vl);
        acc2(A2, A3, vh);
    }

    int e = beg;
    while (e < end && (e & 3)) {                      // peel to int4 alignment
        int s = __ldg(csr + e);
        acc2(B0, B1, __ldg(hs4 + (size_t)s * 16 + h));
        acc2(B2, B3, __ldg(hs4 + (size_t)s * 16 + 8 + h));
        e++;
    }
    for (; e + 4 <= end; e += 4) {
        int4 s = __ldg((const int4*)(csr + e));
        uint4 v0l = __ldg(hs4 + (size_t)s.x * 16 + h);
        uint4 v0h = __ldg(hs4 + (size_t)s.x * 16 + 8 + h);
        uint4 v1l = __ldg(hs4 + (size_t)s.y * 16 + h);
        uint4 v1h = __ldg(hs4 + (size_t)s.y * 16 + 8 + h);
        uint4 v2l = __ldg(hs4 + (size_t)s.z * 16 + h);
        uint4 v2h = __ldg(hs4 + (size_t)s.z * 16 + 8 + h);
        uint4 v3l = __ldg(hs4 + (size_t)s.w * 16 + h);
        uint4 v3h = __ldg(hs4 + (size_t)s.w * 16 + 8 + h);
        acc2(A0, A1, v0l); acc2(A2, A3, v0h);
        acc2(B0, B1, v1l); acc2(B2, B3, v1h);
        acc2(A0, A1, v2l); acc2(A2, A3, v2h);
        acc2(B0, B1, v3l); acc2(B2, B3, v3h);
    }
    for (; e < end; e++) {
        int s = __ldg(csr + e);
        acc2(A0, A1, __ldg(hs4 + (size_t)s * 16 + h));
        acc2(A2, A3, __ldg(hs4 + (size_t)s * 16 + 8 + h));
    }
    float4 L0 = f4add(A0, B0), L1 = f4add(A1, B1);
    float4 H0 = f4add(A2, B2), H1 = f4add(A3, B3);

    // finalize: out = acc*dd + bias (+ relu); lane h covers float4 idx
    // {2h, 2h+1, 2(h+8), 2(h+8)+1}
    const float4* b4 = (const float4*)b;
    float4 bb0 = __ldg(b4 + 2 * h);
    float4 bb1 = __ldg(b4 + 2 * h + 1);
    float4 bb2 = __ldg(b4 + 2 * (h + 8));
    float4 bb3 = __ldg(b4 + 2 * (h + 8) + 1);
    float4 o0, o1, o2, o3;
    o0.x = fmaf(L0.x, dd, bb0.x); o0.y = fmaf(L0.y, dd, bb0.y);
    o0.z = fmaf(L0.z, dd, bb0.z); o0.w = fmaf(L0.w, dd, bb0.w);
    o1.x = fmaf(L1.x, dd, bb1.x); o1.y = fmaf(L1.y, dd, bb1.y);
    o1.z = fmaf(L1.z, dd, bb1.z); o1.w = fmaf(L1.w, dd, bb1.w);
    o2.x = fmaf(H0.x, dd, bb2.x); o2.y = fmaf(H0.y, dd, bb2.y);
    o2.z = fmaf(H0.z, dd, bb2.z); o2.w = fmaf(H0.w, dd, bb2.w);
    o3.x = fmaf(H1.x, dd, bb3.x); o3.y = fmaf(H1.y, dd, bb3.y);
    o3.z = fmaf(H1.z, dd, bb3.z); o3.w = fmaf(H1.w, dd, bb3.w);
    if (do_relu) {
        o0.x = fmaxf(o0.x, 0.f); o0.y = fmaxf(o0.y, 0.f);
        o0.z = fmaxf(o0.z, 0.f); o0.w = fmaxf(o0.w, 0.f);
        o1.x = fmaxf(o1.x, 0.f); o1.y = fmaxf(o1.y, 0.f);
        o1.z = fmaxf(o1.z, 0.f); o1.w = fmaxf(o1.w, 0.f);
        o2.x = fmaxf(o2.x, 0.f); o2.y = fmaxf(o2.y, 0.f);
        o2.z = fmaxf(o2.z, 0.f); o2.w = fmaxf(o2.w, 0.f);
        o3.x = fmaxf(o3.x, 0.f); o3.y = fmaxf(o3.y, 0.f);
        o3.z = fmaxf(o3.z, 0.f); o3.w = fmaxf(o3.w, 0.f);
    }
    float4* orow = (float4*)out + (size_t)node * 32;
    orow[2 * h]           = o0;
    orow[2 * h + 1]       = o1;
    orow[2 * (h + 8)]     = o2;
    orow[2 * (h + 8) + 1] = o3;
}

// ---------------------------------------------------------------------------
// Launch. GEMM (layer 1) stays at launch index 3 for the ncu window.
// ---------------------------------------------------------------------------
extern "C" void kernel_launch(void* const* d_in, const int* in_sizes, int n_in,
                              void* d_out, int out_size) {
    const float* x1  = (const float*)d_in[0];
    const int*   ei1 = (const int*)  d_in[1];
    const float* x2  = (const float*)d_in[2];
    const int*   ei2 = (const int*)  d_in[3];
    const float* W0  = (const float*)d_in[4];
    const float* b0  = (const float*)d_in[5];
    const float* W1  = (const float*)d_in[6];
    const float* b1  = (const float*)d_in[7];
    float* out = (float*)d_out;

    const int* src1 = ei1;
    const int* dst1 = ei1 + N_EDGES;
    const int* src2 = ei2;
    const int* dst2 = ei2 + N_EDGES;

    float *h1, *h2;
    __half *hsA, *hsB;
    uint4* Bq;
    int* cnt;
    cudaGetSymbolAddress((void**)&hsA, g_hsA);
    cudaGetSymbolAddress((void**)&hsB, g_hsB);
    cudaGetSymbolAddress((void**)&h1,  g_h1);
    cudaGetSymbolAddress((void**)&h2,  g_h2);
    cudaGetSymbolAddress((void**)&Bq,  g_Bq);
    cudaGetSymbolAddress((void**)&cnt, g_cnt);

    k_packw<<<16, 256>>>(W0, W1);                              // 0
    k_zero_cnt<<<(2 * N_NODES + 255) / 256, 256>>>();          // 1
    k_count2<<<1024, 256>>>(dst1, dst2);                       // 2
    k_gemm_h16<<<2 * NBLK, 256>>>(x1, x2, Bq, cnt, hsA, hsB);  // 3  (ncu window)
    k_blocksum<<<N_TILES, TILE>>>();                           // 4
    k_scanbase<<<1, 256>>>();                                  // 5
    k_offsets<<<N_TILES, TILE>>>();                            // 6
    k_fill2<<<1024, 256>>>(src1, dst1, src2, dst2);            // 7

    const int AGG_GRID = (2 * N_NODES + 15) / 16;              // 6250 blocks

    k_aggregate<<<AGG_GRID, 128>>>(hsA, hsB, b0, h1, h2, 1);
    k_gemm_h16<<<2 * NBLK, 256>>>(h1, h2, Bq + 2048, cnt, hsA, hsB);
    k_aggregate<<<AGG_GRID, 128>>>(hsA, hsB, b1, out, out + (size_t)N_NODES * DIM, 0);
}